// round 10
// baseline (speedup 1.0000x reference)
#include <cuda_runtime.h>
#include <cuda_bf16.h>

#define FULL 0xFFFFFFFFu
#define LOG2E 1.4426950408889634f

#define NSTG 3                      // pipeline stages
#define TILE_ROWS 16                // rows per tile (8 warps x 2 rows)
#define ROW_BYTES 512               // 128 cols x 4 B
#define ARR_BYTES (TILE_ROWS * ROW_BYTES)   // 8192 per array per tile
#define STAGE_BYTES (4 * ARR_BYTES)         // 32768 per stage

__device__ __forceinline__ float ex2f(float x) {
    float r; asm("ex2.approx.ftz.f32 %0, %1;" : "=f"(r) : "f"(x)); return r;
}

__device__ __forceinline__ float safe_neglog(float p) {
    // reference: where(p > THR, -log(max(p, THR)), 0); p > THR => max(p,THR)==p
    return (p > 9.2885e-30f) ? -__logf(p) : 0.0f;
}

__device__ __forceinline__ void mbar_init(unsigned a, unsigned cnt) {
    asm volatile("mbarrier.init.shared.b64 [%0], %1;" :: "r"(a), "r"(cnt) : "memory");
}
__device__ __forceinline__ void mbar_expect_tx(unsigned a, unsigned bytes) {
    asm volatile("mbarrier.arrive.expect_tx.shared.b64 _, [%0], %1;" :: "r"(a), "r"(bytes) : "memory");
}
__device__ __forceinline__ void mbar_arrive(unsigned a) {
    asm volatile("mbarrier.arrive.shared.b64 _, [%0];" :: "r"(a) : "memory");
}
__device__ __forceinline__ void mbar_wait(unsigned a, unsigned parity) {
    unsigned done;
    asm volatile(
        "{\n\t.reg .pred p;\n\t"
        "mbarrier.try_wait.parity.acquire.cta.shared::cta.b64 p, [%1], %2;\n\t"
        "selp.b32 %0, 1, 0, p;\n\t}"
        : "=r"(done) : "r"(a), "r"(parity) : "memory");
    while (!done) {
        asm volatile(
            "{\n\t.reg .pred p;\n\t"
            "mbarrier.try_wait.parity.acquire.cta.shared::cta.b64 p, [%1], %2, 0x989680;\n\t"
            "selp.b32 %0, 1, 0, p;\n\t}"
            : "=r"(done) : "r"(a), "r"(parity) : "memory");
    }
}
__device__ __forceinline__ void bulk_ld(unsigned dst, const void* src, unsigned bytes, unsigned mbar) {
    asm volatile(
        "cp.async.bulk.shared::cta.global.mbarrier::complete_tx::bytes [%0], [%1], %2, [%3];"
        :: "r"(dst), "l"(src), "r"(bytes), "r"(mbar) : "memory");
}

// Segmented pair compute (proven R7 body): lanes 0-15 own row0, 16-31 row1,
// each lane holds 8 contiguous columns of each array.
__device__ __forceinline__ void wmc_pair(
    const int B1[8], const int B2[8], const float A1[8], const float A2[8],
    int seg, int sl, float* __restrict__ out, int orow0, int K)
{
    const unsigned sh = seg * 16;
    unsigned dmask = 0; int s = 0, a = 1 << 30, b = -1;
    #pragma unroll
    for (int jj = 0; jj < 8; jj++) {
        const unsigned q1 = __ballot_sync(FULL, B1[jj] != 0);
        const unsigned q2 = __ballot_sync(FULL, B2[jj] != 0);
        const unsigned v1 = (q1 >> sh) & 0xFFFFu;
        const unsigned v2 = (q2 >> sh) & 0xFFFFu;
        dmask |= v1 ^ v2;
        s += __popc(v1);
        if (v1) a = min(a, (__ffs(v1) - 1) * 8 + jj);   // first set col of Y1
        if (v2) b = max(b, (31 - __clz(v2)) * 8 + jj);  // last  set col of Y2
    }
    const bool cse1 = (dmask == 0) && (s == 1);
    if (a > 127) a = 0;     // all-zero guard (argmax of zeros = 0)
    if (b < 0)   b = 127;   // all-zero guard (reversed argmax = C-1)
    const int ja = a & 7, la = (a >> 3) + seg * 16;
    const int jb = b & 7, lb = (b >> 3) + seg * 16;

    // No max-subtraction: scores are N(0,1) (|x| < ~6), fp32 exp2 range-safe.
    float z1 = 0.f, z2 = 0.f, cA1 = 0.f, cA2 = 0.f, cB1 = 0.f, cB2 = 0.f;
    #pragma unroll
    for (int jj = 0; jj < 8; jj++) {
        const float e1 = ex2f(A1[jj] * LOG2E); z1 += e1;
        const float e2 = ex2f(A2[jj] * LOG2E); z2 += e2;
        if (jj == ja) { cA1 = e1; cA2 = e2; }
        if (jj == jb) { cB1 = e1; cB2 = e2; }
    }
    #pragma unroll
    for (int o = 8; o; o >>= 1) {
        z1 += __shfl_xor_sync(FULL, z1, o);
        z2 += __shfl_xor_sync(FULL, z2, o);
    }
    const float inv1 = __frcp_rn(z1);
    const float inv2 = __frcp_rn(z2);

    const float e1a = __shfl_sync(FULL, cA1, la);
    const float e2a = __shfl_sync(FULL, cA2, la);
    const float e1b = __shfl_sync(FULL, cB1, lb);
    const float e2b = __shfl_sync(FULL, cB2, lb);

    const float p1a = e1a * inv1, p2a = e2a * inv2;
    const float p1b = e1b * inv1, p2b = e2b * inv2;

    float loss;
    if (cse1) {
        loss = safe_neglog(p1a) + safe_neglog(p2a);
    } else {
        const float prob = 1.f - (1.f - p1a * p2b) * (1.f - p1b * p2a);
        loss = safe_neglog(prob);
    }
    if (sl == 0 && (orow0 + seg) < K) out[orow0 + seg] = loss;
}

__global__ __launch_bounds__(256) void wmc_loss_kernel(
    const float*  __restrict__ s1g, const int* __restrict__ y1g,
    const float*  __restrict__ s2g, const int* __restrict__ y2g,
    float* __restrict__ out, int K, int tiles)
{
    extern __shared__ char sm[];                       // NSTG * 32KB ring
    __shared__ __align__(8) unsigned long long mbar[2 * NSTG];  // full[s], empty[s]

    const int tid  = threadIdx.x;
    const int wb   = tid >> 5;
    const int lane = tid & 31;
    const int seg  = lane >> 4;
    const int sl   = lane & 15;
    const int G    = gridDim.x;
    const int bx   = blockIdx.x;

    unsigned fullb[NSTG], emptyb[NSTG];
    #pragma unroll
    for (int s = 0; s < NSTG; s++) {
        fullb[s]  = (unsigned)__cvta_generic_to_shared(&mbar[s]);
        emptyb[s] = (unsigned)__cvta_generic_to_shared(&mbar[NSTG + s]);
    }
    const unsigned smb = (unsigned)__cvta_generic_to_shared(sm);

    if (tid == 0) {
        #pragma unroll
        for (int s = 0; s < NSTG; s++) {
            mbar_init(fullb[s], 1);     // 1 expect_tx arrival
            mbar_init(emptyb[s], 8);    // 8 warps release
        }
    }
    __syncthreads();

    // ---- remainder rows (K % 16) handled by block 0 via direct LDG ----
    const int rrows = K - tiles * TILE_ROWS;
    if (bx == 0 && rrows > 0 && wb * 2 < rrows) {
        const long maxi = (long)K * 16 - 8;  // clamp (units of 8 floats... see below)
        // pair of rows: tiles*16 + 2*wb (+seg). lane's first float idx:
        long fi = ((long)tiles * TILE_ROWS + 2 * wb) * 128 + lane * 8;
        fi = min(fi, (long)K * 128 - 8);
        const float4* s1p = (const float4*)(s1g + fi);
        const float4* s2p = (const float4*)(s2g + fi);
        const int4*   y1p = (const int4*)(y1g + fi);
        const int4*   y2p = (const int4*)(y2g + fi);
        int4   ya0 = __ldcs(y1p), ya1 = __ldcs(y1p + 1);
        int4   yb0 = __ldcs(y2p), yb1 = __ldcs(y2p + 1);
        float4 sa0 = __ldcs(s1p), sa1 = __ldcs(s1p + 1);
        float4 sb0 = __ldcs(s2p), sb1 = __ldcs(s2p + 1);
        int B1[8] = {ya0.x, ya0.y, ya0.z, ya0.w, ya1.x, ya1.y, ya1.z, ya1.w};
        int B2[8] = {yb0.x, yb0.y, yb0.z, yb0.w, yb1.x, yb1.y, yb1.z, yb1.w};
        float A1[8] = {sa0.x, sa0.y, sa0.z, sa0.w, sa1.x, sa1.y, sa1.z, sa1.w};
        float A2[8] = {sb0.x, sb0.y, sb0.z, sb0.w, sb1.x, sb1.y, sb1.z, sb1.w};
        wmc_pair(B1, B2, A1, A2, seg, sl, out, tiles * TILE_ROWS + 2 * wb, K);
    }

    // ---- prologue: fill the ring ----
    if (tid == 0) {
        #pragma unroll
        for (int t = 0; t < NSTG; t++) {
            const long g = bx + (long)t * G;
            if (g < tiles) {
                const unsigned dst = smb + t * STAGE_BYTES;
                const long go = g * ARR_BYTES;      // byte offset per array
                mbar_expect_tx(fullb[t], STAGE_BYTES);
                bulk_ld(dst,                 (const char*)y1g + go, ARR_BYTES, fullb[t]);
                bulk_ld(dst + ARR_BYTES,     (const char*)y2g + go, ARR_BYTES, fullb[t]);
                bulk_ld(dst + 2 * ARR_BYTES, (const char*)s1g + go, ARR_BYTES, fullb[t]);
                bulk_ld(dst + 3 * ARR_BYTES, (const char*)s2g + go, ARR_BYTES, fullb[t]);
            }
        }
    }

    // ---- main pipeline ----
    const int row = 2 * wb + seg;
    const int off = row * ROW_BYTES + sl * 32;
    for (int t = 0; ; t++) {
        const long g = bx + (long)t * G;
        if (g >= tiles) break;
        const int slot = t % NSTG;
        const unsigned pf = (unsigned)((t / NSTG) & 1);

        mbar_wait(fullb[slot], pf);

        const char* stp = sm + slot * STAGE_BYTES;
        const int4*   y1p = (const int4*)(stp + off);
        const int4*   y2p = (const int4*)(stp + ARR_BYTES + off);
        const float4* s1p = (const float4*)(stp + 2 * ARR_BYTES + off);
        const float4* s2p = (const float4*)(stp + 3 * ARR_BYTES + off);
        const int4   ya0 = y1p[0], ya1 = y1p[1];
        const int4   yb0 = y2p[0], yb1 = y2p[1];
        const float4 sa0 = s1p[0], sa1 = s1p[1];
        const float4 sb0 = s2p[0], sb1 = s2p[1];

        int B1[8] = {ya0.x, ya0.y, ya0.z, ya0.w, ya1.x, ya1.y, ya1.z, ya1.w};
        int B2[8] = {yb0.x, yb0.y, yb0.z, yb0.w, yb1.x, yb1.y, yb1.z, yb1.w};
        float A1[8] = {sa0.x, sa0.y, sa0.z, sa0.w, sa1.x, sa1.y, sa1.z, sa1.w};
        float A2[8] = {sb0.x, sb0.y, sb0.z, sb0.w, sb1.x, sb1.y, sb1.z, sb1.w};
        wmc_pair(B1, B2, A1, A2, seg, sl, out, (int)g * TILE_ROWS + 2 * wb, K);

        if (lane == 0) mbar_arrive(emptyb[slot]);    // warp done with slot

        // producer: refill this slot for tile t+NSTG once all 8 warps released it
        const long gn = bx + (long)(t + NSTG) * G;
        if (tid == 0 && gn < tiles) {
            mbar_wait(emptyb[slot], (unsigned)((t / NSTG) & 1));
            const unsigned dst = smb + slot * STAGE_BYTES;
            const long go = gn * ARR_BYTES;
            mbar_expect_tx(fullb[slot], STAGE_BYTES);
            bulk_ld(dst,                 (const char*)y1g + go, ARR_BYTES, fullb[slot]);
            bulk_ld(dst + ARR_BYTES,     (const char*)y2g + go, ARR_BYTES, fullb[slot]);
            bulk_ld(dst + 2 * ARR_BYTES, (const char*)s1g + go, ARR_BYTES, fullb[slot]);
            bulk_ld(dst + 3 * ARR_BYTES, (const char*)s2g + go, ARR_BYTES, fullb[slot]);
        }
    }
}

extern "C" void kernel_launch(void* const* d_in, const int* in_sizes, int n_in,
                              void* d_out, int out_size)
{
    const int K = in_sizes[0] / 128;           // rows; C = 128
    const int tiles = K / TILE_ROWS;           // full 16-row tiles
    const int smem = NSTG * STAGE_BYTES;       // 96 KB -> 2 blocks/SM
    cudaFuncSetAttribute(wmc_loss_kernel,
                         cudaFuncAttributeMaxDynamicSharedMemorySize, smem);
    int blocks = 296;                           // persistent, 2 per SM
    if (tiles > 0 && blocks > tiles) blocks = tiles;
    if (tiles == 0) blocks = 1;                 // remainder-only path
    wmc_loss_kernel<<<blocks, 256, smem>>>(
        (const float*)d_in[0], (const int*)d_in[1],
        (const float*)d_in[2], (const int*)d_in[3],
        (float*)d_out, K, tiles);
}

// round 11
// speedup vs baseline: 1.3873x; 1.3873x over previous
#include <cuda_runtime.h>
#include <cuda_bf16.h>

#define FULL 0xFFFFFFFFu
#define LOG2E 1.4426950408889634f

__device__ __forceinline__ float ex2f(float x) {
    float r; asm("ex2.approx.ftz.f32 %0, %1;" : "=f"(r) : "f"(x)); return r;
}

__device__ __forceinline__ float safe_neglog(float p) {
    // reference: where(p > THR, -log(max(p, THR)), 0); p > THR => max(p,THR)==p
    return (p > 9.2885e-30f) ? -__logf(p) : 0.0f;
}

// 2 rows per warp, segmented: lanes 0-15 own row0, lanes 16-31 own row1.
// Each lane holds 8 contiguous columns (2 float4 loads, coalesced across warp).
__global__ __launch_bounds__(256) void wmc_loss_kernel(
    const float4* __restrict__ s1g, const int4* __restrict__ y1g,
    const float4* __restrict__ s2g, const int4* __restrict__ y2g,
    float* __restrict__ out, int K)
{
    const int w    = (blockIdx.x * blockDim.x + threadIdx.x) >> 5;  // warp id
    const int lane = threadIdx.x & 31;
    const int seg  = lane >> 4;          // which row of the pair this lane owns
    const int sl   = lane & 15;          // lane within segment
    const int row0 = w * 2;
    if (row0 >= K) return;

    // pair spans 64 float4s; lane covers float4 idx {2*lane, 2*lane+1}
    // = row 'seg', columns sl*8 .. sl*8+7
    const long i0 = (long)row0 * 32 + lane * 2;
    const long i1 = i0 + 1;

    // ---- front-batched: 8 independent 16B streaming loads (MLP=8);
    //      Y first (consumed first by the ballots) ----
    const int4   ya0 = __ldcs(y1g + i0), ya1 = __ldcs(y1g + i1);
    const int4   yb0 = __ldcs(y2g + i0), yb1 = __ldcs(y2g + i1);
    const float4 sa0 = __ldcs(s1g + i0), sa1 = __ldcs(s1g + i1);
    const float4 sb0 = __ldcs(s2g + i0), sb1 = __ldcs(s2g + i1);

    int B1[8] = {ya0.x, ya0.y, ya0.z, ya0.w, ya1.x, ya1.y, ya1.z, ya1.w};
    int B2[8] = {yb0.x, yb0.y, yb0.z, yb0.w, yb1.x, yb1.y, yb1.z, yb1.w};

    // ---- ballots carry BOTH rows (low 16 bits = row0, high = row1);
    //      masks consumed immediately so Y regs die fast ----
    const unsigned sh = seg * 16;
    unsigned dmask = 0; int s = 0, a = 1 << 30, b = -1;
    #pragma unroll
    for (int jj = 0; jj < 8; jj++) {
        const unsigned q1 = __ballot_sync(FULL, B1[jj] != 0);
        const unsigned q2 = __ballot_sync(FULL, B2[jj] != 0);
        const unsigned v1 = (q1 >> sh) & 0xFFFFu;   // my row's Y1 bits for col jj
        const unsigned v2 = (q2 >> sh) & 0xFFFFu;   // my row's Y2 bits
        dmask |= v1 ^ v2;
        s += __popc(v1);
        if (v1) a = min(a, (__ffs(v1) - 1) * 8 + jj);       // first set col of Y1
        if (v2) b = max(b, (31 - __clz(v2)) * 8 + jj);      // last  set col of Y2
    }
    const bool cse1 = (dmask == 0) && (s == 1);
    if (a > 127) a = 0;     // all-zero guard (argmax of zeros = 0)
    if (b < 0)   b = 127;   // all-zero guard (reversed argmax = C-1)
    const int ja = a & 7, la = (a >> 3) + seg * 16;  // source lane in my segment
    const int jb = b & 7, lb = (b >> 3) + seg * 16;

    // ---- exp + partial sums with on-the-fly gather selection ----
    // No max-subtraction: scores are N(0,1) (|x| < ~6), fp32 exp2 range-safe.
    float A1[8] = {sa0.x, sa0.y, sa0.z, sa0.w, sa1.x, sa1.y, sa1.z, sa1.w};
    float A2[8] = {sb0.x, sb0.y, sb0.z, sb0.w, sb1.x, sb1.y, sb1.z, sb1.w};
    float z1 = 0.f, z2 = 0.f, cA1 = 0.f, cA2 = 0.f, cB1 = 0.f, cB2 = 0.f;
    #pragma unroll
    for (int jj = 0; jj < 8; jj++) {
        const float e1 = ex2f(A1[jj] * LOG2E); z1 += e1;
        const float e2 = ex2f(A2[jj] * LOG2E); z2 += e2;
        if (jj == ja) { cA1 = e1; cA2 = e2; }
        if (jj == jb) { cB1 = e1; cB2 = e2; }
    }

    // ---- segmented 4-level butterflies: both rows reduced in one chain ----
    #pragma unroll
    for (int o = 8; o; o >>= 1) {
        z1 += __shfl_xor_sync(FULL, z1, o);
        z2 += __shfl_xor_sync(FULL, z2, o);
    }
    const float inv1 = __frcp_rn(z1);
    const float inv2 = __frcp_rn(z2);

    // ---- per-segment gathers (per-lane source index is fine for SHFL.IDX) ----
    const float e1a = __shfl_sync(FULL, cA1, la);
    const float e2a = __shfl_sync(FULL, cA2, la);
    const float e1b = __shfl_sync(FULL, cB1, lb);
    const float e2b = __shfl_sync(FULL, cB2, lb);

    const float p1a = e1a * inv1, p2a = e2a * inv2;
    const float p1b = e1b * inv1, p2b = e2b * inv2;

    // case1 (equal one-hot):      -log p1a - log p2a
    // case2 + default (two distinct positions a,b):
    //      1 - (1 - P1[a]P2[b])(1 - P1[b]P2[a])
    float loss;
    if (cse1) {
        loss = safe_neglog(p1a) + safe_neglog(p2a);
    } else {
        const float prob = 1.f - (1.f - p1a * p2b) * (1.f - p1b * p2a);
        loss = safe_neglog(prob);
    }

    if (sl == 0 && (row0 + seg) < K) out[row0 + seg] = loss;
}

extern "C" void kernel_launch(void* const* d_in, const int* in_sizes, int n_in,
                              void* d_out, int out_size)
{
    const int K = in_sizes[0] / 128;          // rows; C = 128
    const int warps   = (K + 1) / 2;          // 2 rows per warp
    const int threads = 256;
    const int blocks  = (warps * 32 + threads - 1) / threads;
    wmc_loss_kernel<<<blocks, threads>>>(
        (const float4*)d_in[0], (const int4*)d_in[1],
        (const float4*)d_in[2], (const int4*)d_in[3],
        (float*)d_out, K);
}

// round 12
// speedup vs baseline: 1.3884x; 1.0008x over previous
#include <cuda_runtime.h>
#include <cuda_bf16.h>

#define FULL 0xFFFFFFFFu
#define LOG2E 1.4426950408889634f

__device__ __forceinline__ float ex2f(float x) {
    float r; asm("ex2.approx.ftz.f32 %0, %1;" : "=f"(r) : "f"(x)); return r;
}

__device__ __forceinline__ float safe_neglog(float p) {
    // reference: where(p > THR, -log(max(p, THR)), 0); p > THR => max(p,THR)==p
    return (p > 9.2885e-30f) ? -__logf(p) : 0.0f;
}

// 2 rows per warp, segmented: lanes 0-15 own row0, lanes 16-31 own row1.
// Each lane holds 8 contiguous columns (2 float4 loads, coalesced across warp).
__global__ __launch_bounds__(256) void wmc_loss_kernel(
    const float4* __restrict__ s1g, const int4* __restrict__ y1g,
    const float4* __restrict__ s2g, const int4* __restrict__ y2g,
    float* __restrict__ out, int K)
{
    const int w    = (blockIdx.x * blockDim.x + threadIdx.x) >> 5;  // warp id
    const int lane = threadIdx.x & 31;
    const int seg  = lane >> 4;          // which row of the pair this lane owns
    const int sl   = lane & 15;          // lane within segment
    const int row0 = w * 2;
    if (row0 >= K) return;

    // pair spans 64 float4s; lane covers float4 idx {2*lane, 2*lane+1}
    // = row 'seg', columns sl*8 .. sl*8+7
    const long i0 = (long)row0 * 32 + lane * 2;
    const long i1 = i0 + 1;

    // ---- front-batched: 8 independent 16B streaming loads (MLP=8);
    //      Y first (consumed first) ----
    const int4   ya0 = __ldcs(y1g + i0), ya1 = __ldcs(y1g + i1);
    const int4   yb0 = __ldcs(y2g + i0), yb1 = __ldcs(y2g + i1);
    const float4 sa0 = __ldcs(s1g + i0), sa1 = __ldcs(s1g + i1);
    const float4 sb0 = __ldcs(s2g + i0), sb1 = __ldcs(s2g + i1);

    int B1[8] = {ya0.x, ya0.y, ya0.z, ya0.w, ya1.x, ya1.y, ya1.z, ya1.w};
    int B2[8] = {yb0.x, yb0.y, yb0.z, yb0.w, yb1.x, yb1.y, yb1.z, yb1.w};

    // ---- per-lane 8-bit occupancy masks over this lane's 8 columns ----
    unsigned m1 = 0, m2 = 0;
    #pragma unroll
    for (int jj = 0; jj < 8; jj++) {
        m1 |= (unsigned)(B1[jj] != 0) << jj;
        m2 |= (unsigned)(B2[jj] != 0) << jj;
    }

    // ---- 4 ballots replace the old 16: any(Y1), any(Y2), diff, multi ----
    const unsigned sh = seg * 16;
    const unsigned balA1 = __ballot_sync(FULL, m1 != 0);
    const unsigned balA2 = __ballot_sync(FULL, m2 != 0);
    const unsigned balNE = __ballot_sync(FULL, m1 != m2);
    const unsigned balML = __ballot_sync(FULL, (m1 & (m1 - 1)) != 0);  // popc>=2

    const unsigned v1 = (balA1 >> sh) & 0xFFFFu;   // my row's lanes with Y1 bits
    const unsigned v2 = (balA2 >> sh) & 0xFFFFu;   // my row's lanes with Y2 bits
    const bool eq     = ((balNE >> sh) & 0xFFFFu) == 0;
    // s == 1  <=>  exactly one lane has bits, and no lane has >=2 bits
    const bool cse1 = eq && (__popc(v1) == 1) && (((balML >> sh) & 0xFFFFu) == 0);

    // a = first set col of Y1: la = first lane of segment with bits; ja = that
    // lane's first private bit. b = last set col of Y2, symmetric.
    const int la = (v1 ? (__ffs(v1) - 1) : 0) + seg * 16;
    const int lb = (v2 ? (31 - __clz(v2)) : 15) + seg * 16;
    const int f1 = __ffs(m1) - 1;           // -1 if none
    const int g2 = 31 - __clz(m2);          // -1 if none (clz(0)=32)
    const int ja = max(__shfl_sync(FULL, f1, la), 0);   // all-zero guard -> col 0
    const int jbv = __shfl_sync(FULL, g2, lb);
    const int jb = (jbv < 0) ? 7 : jbv;                 // all-zero guard -> col 127

    // ---- exp + partial sums with on-the-fly gather selection ----
    // No max-subtraction: scores are N(0,1) (|x| < ~6), fp32 exp2 range-safe.
    float A1[8] = {sa0.x, sa0.y, sa0.z, sa0.w, sa1.x, sa1.y, sa1.z, sa1.w};
    float A2[8] = {sb0.x, sb0.y, sb0.z, sb0.w, sb1.x, sb1.y, sb1.z, sb1.w};
    float z1 = 0.f, z2 = 0.f, cA1 = 0.f, cA2 = 0.f, cB1 = 0.f, cB2 = 0.f;
    #pragma unroll
    for (int jj = 0; jj < 8; jj++) {
        const float e1 = ex2f(A1[jj] * LOG2E); z1 += e1;
        const float e2 = ex2f(A2[jj] * LOG2E); z2 += e2;
        if (jj == ja) { cA1 = e1; cA2 = e2; }
        if (jj == jb) { cB1 = e1; cB2 = e2; }
    }

    // ---- segmented 4-level butterflies: both rows reduced in one chain ----
    #pragma unroll
    for (int o = 8; o; o >>= 1) {
        z1 += __shfl_xor_sync(FULL, z1, o);
        z2 += __shfl_xor_sync(FULL, z2, o);
    }
    const float inv1 = __frcp_rn(z1);
    const float inv2 = __frcp_rn(z2);

    // ---- per-segment gathers (per-lane source index is fine for SHFL.IDX) ----
    const float e1a = __shfl_sync(FULL, cA1, la);
    const float e2a = __shfl_sync(FULL, cA2, la);
    const float e1b = __shfl_sync(FULL, cB1, lb);
    const float e2b = __shfl_sync(FULL, cB2, lb);

    const float p1a = e1a * inv1, p2a = e2a * inv2;
    const float p1b = e1b * inv1, p2b = e2b * inv2;

    // case1 (equal one-hot):      -log p1a - log p2a
    // case2 + default (two distinct positions a,b):
    //      1 - (1 - P1[a]P2[b])(1 - P1[b]P2[a])
    float loss;
    if (cse1) {
        loss = safe_neglog(p1a) + safe_neglog(p2a);
    } else {
        const float prob = 1.f - (1.f - p1a * p2b) * (1.f - p1b * p2a);
        loss = safe_neglog(prob);
    }

    if (sl == 0 && (row0 + seg) < K) out[row0 + seg] = loss;
}

extern "C" void kernel_launch(void* const* d_in, const int* in_sizes, int n_in,
                              void* d_out, int out_size)
{
    const int K = in_sizes[0] / 128;          // rows; C = 128
    const int warps   = (K + 1) / 2;          // 2 rows per warp
    const int threads = 256;
    const int blocks  = (warps * 32 + threads - 1) / threads;
    wmc_loss_kernel<<<blocks, threads>>>(
        (const float4*)d_in[0], (const int4*)d_in[1],
        (const float4*)d_in[2], (const int4*)d_in[3],
        (float*)d_out, K);
}